// round 13
// baseline (speedup 1.0000x reference)
#include <cuda_runtime.h>
#include <cuda_bf16.h>
#include <math.h>

#define Bv 32
#define Hv 128
#define Wv 128
#define Cv 10
#define Kv 32
#define CH 32

#define A_ELEMS (Bv*Hv*Wv*Kv)
#define T_FEATS 17

// -------------------- scratch --------------------
__device__ __align__(256) float g_r1 [Bv*Hv*Wv*CH];
__device__ __align__(256) float g_phi[Bv*Hv*Wv*CH];
__device__ __align__(256) float g_aff[Bv*Hv*Wv*4];
__device__ __align__(256) float g_A0 [Hv*Wv*Kv];
__device__ __align__(256) float g_part[Bv*Hv*Kv*13];

// -------------------- f32x2 helpers --------------------
__device__ __forceinline__ unsigned long long pack2(float lo, float hi) {
    unsigned long long r;
    asm("mov.b64 %0,{%1,%2};" : "=l"(r) : "f"(lo), "f"(hi));
    return r;
}
__device__ __forceinline__ float2 unpack2(unsigned long long v) {
    float2 r;
    asm("mov.b64 {%0,%1},%2;" : "=f"(r.x), "=f"(r.y) : "l"(v));
    return r;
}
__device__ __forceinline__ void ffma2(unsigned long long &d,
                                      unsigned long long a, unsigned long long b) {
    asm("fma.rn.f32x2 %0, %1, %2, %0;" : "+l"(d) : "l"(a), "l"(b));
}
__device__ __forceinline__ unsigned long long fma2o(unsigned long long a,
                                                    unsigned long long b,
                                                    unsigned long long c) {
    unsigned long long r;
    asm("fma.rn.f32x2 %0, %1, %2, %3;" : "=l"(r) : "l"(a), "l"(b), "l"(c));
    return r;
}
__device__ __forceinline__ unsigned long long mul2(unsigned long long a, unsigned long long b) {
    unsigned long long r;
    asm("mul.rn.f32x2 %0, %1, %2;" : "=l"(r) : "l"(a), "l"(b));
    return r;
}
__device__ __forceinline__ float ex2(float x) {
    float r;
    asm("ex2.approx.ftz.f32 %0, %1;" : "=f"(r) : "f"(x));
    return r;
}

// ============================================================================
// init A0
// ============================================================================
__global__ __launch_bounds__(128) void initA_kernel(float* __restrict__ A0)
{
    int h = blockIdx.x, w = threadIdx.x;
    float fh = (float)h, fw = (float)w;
    float lg[Kv]; float m = -1e30f;
    #pragma unroll
    for (int k = 0; k < Kv; k++) {
        float sh = ((k >> 3) + 0.5f) * 32.f;
        float sw = ((k & 7)  + 0.5f) * 16.f;
        float dh = fh - sh, dw = fw - sw;
        lg[k] = -(dh*dh + dw*dw) * (1.f/512.f);
        m = fmaxf(m, lg[k]);
    }
    float s = 0.f;
    #pragma unroll
    for (int k = 0; k < Kv; k++) { lg[k] = __expf(lg[k] - m); s += lg[k]; }
    float inv = 1.f / s;
    float4* dst = (float4*)(A0 + (size_t)(h*Wv + w)*Kv);
    #pragma unroll
    for (int g = 0; g < 8; g++)
        dst[g] = make_float4(lg[4*g]*inv, lg[4*g+1]*inv, lg[4*g+2]*inv, lg[4*g+3]*inv);
}

// ============================================================================
// fused conv1+conv2+conv3 -> phi  (R9 best-measured variant: smem weights,
// 256 threads, thread = 2 strided pixels x 16 output channels)
// ============================================================================
#define R1PITCH 343
#define Y2PITCH 257
#define OFF_W1  0
#define OFF_B1  (OFF_W1 + 9*Cv*CH)
#define OFF_W2  (OFF_B1 + 32)
#define OFF_W3  (OFF_W2 + 9*CH*CH)
#define OFF_B2  (OFF_W3 + CH*CH)
#define OFF_B3  (OFF_B2 + 32)
#define OFF_X   (OFF_B3 + 32)
#define OFF_R1  (OFF_X + 400)
#define CONV_F  (OFF_R1 + CH*R1PITCH)
#define CONV_SMEM (CONV_F * 4)

__global__ __launch_bounds__(256, 2) void conv123_kernel(
    const int* __restrict__ X,
    const float* __restrict__ w1, const float* __restrict__ b1,
    const float* __restrict__ w2, const float* __restrict__ b2,
    const float* __restrict__ w3, const float* __restrict__ b3,
    float* __restrict__ phi)
{
    extern __shared__ float smem[];
    float* s_w1 = smem + OFF_W1;
    float* s_b1 = smem + OFF_B1;
    float* s_w2 = smem + OFF_W2;
    float* s_w3 = smem + OFF_W3;
    float* s_b2 = smem + OFF_B2;
    float* s_b3 = smem + OFF_B3;
    int*   s_x  = (int*)(smem + OFF_X);
    float* s_r1 = smem + OFF_R1;
    float* s_y2 = smem + OFF_R1;

    int b = blockIdx.x, h0 = blockIdx.y*16, w0 = blockIdx.z*16;
    int tid = threadIdx.x;

    for (int i = tid; i < 9*Cv*CH; i += 256) s_w1[i] = w1[i];
    for (int i = tid; i < 9*CH*CH; i += 256) s_w2[i] = w2[i];
    for (int i = tid; i < CH*CH;   i += 256) s_w3[i] = w3[i];
    if (tid < 32) { s_b1[tid] = b1[tid]; s_b2[tid] = b2[tid]; s_b3[tid] = b3[tid]; }

    for (int p = tid; p < 400; p += 256) {
        int ly = p / 20, lx = p % 20;
        int gh = h0 + ly - 2, gw = w0 + lx - 2;
        s_x[p] = (gh >= 0 && gh < Hv && gw >= 0 && gw < Wv) ? X[(b*Hv+gh)*Wv+gw] : -1;
    }
    __syncthreads();

    {
        int co = tid & 31, wg = tid >> 5;
        for (int p = wg; p < 18*18; p += 8) {
            int lh = p / 18, lw = p % 18;
            float acc1 = s_b1[co];
            #pragma unroll
            for (int dy = 0; dy < 3; dy++) {
                #pragma unroll
                for (int dx = 0; dx < 3; dx++) {
                    int c = s_x[(lh+dy)*20 + (lw+dx)];
                    if (c >= 0) acc1 += s_w1[((dy*3+dx)*Cv + c)*CH + co];
                }
            }
            s_r1[co*R1PITCH + lh*19 + lw] = fmaxf(acc1, 0.f);
        }
    }
    __syncthreads();

    int co_half = tid >> 7;
    int pg = tid & 127;
    int px0 = pg, px1 = pg + 128;
    int plh0 = px0 >> 4, plw0 = px0 & 15;
    int plh1 = px1 >> 4, plw1 = px1 & 15;
    int off0 = plh0*19 + plw0, off1 = plh1*19 + plw1;

    unsigned long long acc[16];
    #pragma unroll
    for (int j = 0; j < 2; j++)
        #pragma unroll
        for (int g = 0; g < 8; g++)
            acc[j*8+g] = pack2(s_b2[co_half*16+2*g], s_b2[co_half*16+2*g+1]);

    #pragma unroll
    for (int pos = 0; pos < 9; pos++) {
        int dy = pos / 3, dx = pos % 3;
        const float* ibase = s_r1 + dy*19 + dx;
        #pragma unroll 4
        for (int ci = 0; ci < CH; ci++) {
            const float* ib = ibase + ci*R1PITCH;
            float v0 = ib[off0];
            float v1 = ib[off1];
            const ulonglong2* wp = (const ulonglong2*)(s_w2 + pos*CH*CH + ci*CH + co_half*16);
            ulonglong2 wA = wp[0], wB = wp[1], wC = wp[2], wD = wp[3];
            unsigned long long vv0 = pack2(v0,v0), vv1 = pack2(v1,v1);
            ffma2(acc[0], vv0, wA.x); ffma2(acc[1], vv0, wA.y);
            ffma2(acc[2], vv0, wB.x); ffma2(acc[3], vv0, wB.y);
            ffma2(acc[4], vv0, wC.x); ffma2(acc[5], vv0, wC.y);
            ffma2(acc[6], vv0, wD.x); ffma2(acc[7], vv0, wD.y);
            ffma2(acc[8],  vv1, wA.x); ffma2(acc[9],  vv1, wA.y);
            ffma2(acc[10], vv1, wB.x); ffma2(acc[11], vv1, wB.y);
            ffma2(acc[12], vv1, wC.x); ffma2(acc[13], vv1, wC.y);
            ffma2(acc[14], vv1, wD.x); ffma2(acc[15], vv1, wD.y);
        }
    }
    __syncthreads();

    #pragma unroll
    for (int g = 0; g < 8; g++) {
        float2 v0 = unpack2(acc[g]);
        float2 v1 = unpack2(acc[8+g]);
        s_y2[(co_half*16 + 2*g  )*Y2PITCH + px0] = fmaxf(v0.x, 0.f);
        s_y2[(co_half*16 + 2*g+1)*Y2PITCH + px0] = fmaxf(v0.y, 0.f);
        s_y2[(co_half*16 + 2*g  )*Y2PITCH + px1] = fmaxf(v1.x, 0.f);
        s_y2[(co_half*16 + 2*g+1)*Y2PITCH + px1] = fmaxf(v1.y, 0.f);
    }
    __syncthreads();

    #pragma unroll
    for (int j = 0; j < 2; j++)
        #pragma unroll
        for (int g = 0; g < 8; g++)
            acc[j*8+g] = pack2(s_b3[co_half*16+2*g], s_b3[co_half*16+2*g+1]);

    #pragma unroll 4
    for (int ci = 0; ci < CH; ci++) {
        const float* ib = s_y2 + ci*Y2PITCH;
        float v0 = ib[px0], v1 = ib[px1];
        const ulonglong2* wp = (const ulonglong2*)(s_w3 + ci*CH + co_half*16);
        ulonglong2 wA = wp[0], wB = wp[1], wC = wp[2], wD = wp[3];
        unsigned long long vv0 = pack2(v0,v0), vv1 = pack2(v1,v1);
        ffma2(acc[0], vv0, wA.x); ffma2(acc[1], vv0, wA.y);
        ffma2(acc[2], vv0, wB.x); ffma2(acc[3], vv0, wB.y);
        ffma2(acc[4], vv0, wC.x); ffma2(acc[5], vv0, wC.y);
        ffma2(acc[6], vv0, wD.x); ffma2(acc[7], vv0, wD.y);
        ffma2(acc[8],  vv1, wA.x); ffma2(acc[9],  vv1, wA.y);
        ffma2(acc[10], vv1, wB.x); ffma2(acc[11], vv1, wB.y);
        ffma2(acc[12], vv1, wC.x); ffma2(acc[13], vv1, wC.y);
        ffma2(acc[14], vv1, wD.x); ffma2(acc[15], vv1, wD.y);
    }

    {
        float* dp0 = phi + (size_t)((b*Hv + h0+plh0)*Wv + w0+plw0)*CH + co_half*16;
        float* dp1 = phi + (size_t)((b*Hv + h0+plh1)*Wv + w0+plw1)*CH + co_half*16;
        float4* d40 = (float4*)dp0;
        float4* d41 = (float4*)dp1;
        #pragma unroll
        for (int g = 0; g < 4; g++) {
            float2 lo0 = unpack2(acc[2*g]);
            float2 hi0 = unpack2(acc[2*g+1]);
            d40[g] = make_float4(lo0.x, lo0.y, hi0.x, hi0.y);
            float2 lo1 = unpack2(acc[8+2*g]);
            float2 hi1 = unpack2(acc[8+2*g+1]);
            d41[g] = make_float4(lo1.x, lo1.y, hi1.x, hi1.y);
        }
    }
}

// ============================================================================
// lane-split neighbor affinity (unchanged)
// ============================================================================
#define AFF_SCALE 2.88539008177792681f   // 2 * log2(e)

__global__ __launch_bounds__(128, 8) void aff_ls_kernel(
    const float* __restrict__ phi, float* __restrict__ aff)
{
    int tid = threadIdx.x, lane = tid & 31, wrp = tid >> 5;
    int kq = lane & 3, pig = lane >> 2;
    int bidx = blockIdx.x;
    int wc = bidx & 3, h = (bidx >> 2) & 127, b = bidx >> 9;
    int w = wc*32 + wrp*8 + pig;
    size_t pix = (size_t)(b*Hv + h)*Wv + w;
    size_t rowb = pix*CH + kq*8;

    const ulonglong2* pc = (const ulonglong2*)(phi + rowb);
    ulonglong2 c0 = pc[0], c1 = pc[1];
    unsigned long long M1 = pack2(-1.f, -1.f);

    long offs[4];
    offs[0] = (h+1 < Hv) ? (long)Wv*CH : 0;
    offs[1] = (h   >= 1) ? -(long)Wv*CH : 0;
    offs[2] = (w+1 < Wv) ? (long)CH : 0;
    offs[3] = (w   >= 1) ? -(long)CH : 0;

    float s[4];
    #pragma unroll
    for (int d = 0; d < 4; d++) {
        const ulonglong2* pn = (const ulonglong2*)(phi + rowb + offs[d]);
        ulonglong2 n0 = pn[0], n1 = pn[1];
        unsigned long long a = pack2(0.f, 0.f);
        unsigned long long t0 = fma2o(n0.x, M1, c0.x); a = fma2o(t0, t0, a);
        unsigned long long t1 = fma2o(n0.y, M1, c0.y); a = fma2o(t1, t1, a);
        unsigned long long t2 = fma2o(n1.x, M1, c1.x); a = fma2o(t2, t2, a);
        unsigned long long t3 = fma2o(n1.y, M1, c1.y); a = fma2o(t3, t3, a);
        float2 p = unpack2(a);
        s[d] = p.x + p.y;
    }
    #pragma unroll
    for (int d = 0; d < 4; d++) {
        s[d] += __shfl_xor_sync(0xffffffffu, s[d], 1);
        s[d] += __shfl_xor_sync(0xffffffffu, s[d], 2);
    }
    if (kq == 0) {
        float4 wd;
        wd.x = (h+1 < Hv) ? AFF_SCALE * __expf(-2.f*s[0]) : 0.f;
        wd.y = (h   >= 1) ? AFF_SCALE * __expf(-2.f*s[1]) : 0.f;
        wd.z = (w+1 < Wv) ? AFF_SCALE * __expf(-2.f*s[2]) : 0.f;
        wd.w = (w   >= 1) ? AFF_SCALE * __expf(-2.f*s[3]) : 0.f;
        ((float4*)aff)[pix] = wd;
    }
}

// ============================================================================
// fused 2x message pass, lane-split smem layout [px][ch] (natural, no
// transpose). 16x16 output tile, 20x20 halo region, double-buffered.
// Task = (pixel, k-quarter); 4 lanes per pixel, softmax sum via 2 shfl.
// Out-of-image halo: A=0, aff=0 -> never propagates into in-image pixels.
// ============================================================================
#define TS 20
#define TSPIX 400
#define MP2LS_SMEM (TSPIX*CH*4*2 + TSPIX*16)   // sA + sB + aff = 108800 B

__global__ __launch_bounds__(256, 2) void msgpass2_ls_kernel(
    const float* __restrict__ Ain, int bstride,
    const float* __restrict__ aff, float* __restrict__ Aout)
{
    extern __shared__ float smem[];
    float*  sA    = smem;                     // [400][32]
    float*  sB    = smem + TSPIX*CH;          // [400][32]
    float4* s_aff = (float4*)(smem + 2*TSPIX*CH);

    int tid = threadIdx.x;
    int b   = blockIdx.z;
    int g0h = blockIdx.y*16 - 2;
    int g0w = blockIdx.x*16 - 2;

    const float* Abase = Ain + (size_t)b * bstride;

    // load A tile: 400 px x 8 float4 chunks = 3200 tasks
    for (int i = tid; i < TSPIX*8; i += 256) {
        int px = i >> 3, c = i & 7;
        int gh = g0h + px / TS, gw = g0w + px % TS;
        float4 v = make_float4(0.f, 0.f, 0.f, 0.f);
        if (gh >= 0 && gh < Hv && gw >= 0 && gw < Wv)
            v = ((const float4*)(Abase + (size_t)(gh*Wv + gw)*Kv))[c];
        ((float4*)sA)[px*8 + c] = v;
    }
    for (int i = tid; i < TSPIX; i += 256) {
        int gh = g0h + i / TS, gw = g0w + i % TS;
        s_aff[i] = (gh >= 0 && gh < Hv && gw >= 0 && gw < Wv)
                 ? ((const float4*)aff)[(size_t)(b*Hv + gh)*Wv + gw]
                 : make_float4(0.f, 0.f, 0.f, 0.f);
    }
    __syncthreads();

    // ---- pass 0: 18x18 interior (offset 1), sA -> sB. 1296 tasks, 6 iters,
    // all threads run all iters (clamped) so shfl masks stay full.
    #pragma unroll
    for (int it = 0; it < 6; it++) {
        int i = tid + it*256;
        bool valid = (i < 18*18*4);
        int ii = valid ? i : 0;
        int px18 = ii >> 2, kq = ii & 3;
        int pc = (1 + px18/18)*TS + (1 + px18%18);
        float4 wd = s_aff[pc];
        unsigned long long wx = pack2(wd.x, wd.x), wy = pack2(wd.y, wd.y);
        unsigned long long wz = pack2(wd.z, wd.z), wwv = pack2(wd.w, wd.w);
        const ulonglong2* p = (const ulonglong2*)sA;
        int s0 = pc*8 + kq*2;
        ulonglong2 U0 = p[s0 + 8*TS],  U1 = p[s0 + 8*TS + 1];
        ulonglong2 D0 = p[s0 - 8*TS],  D1 = p[s0 - 8*TS + 1];
        ulonglong2 R0 = p[s0 + 8],     R1 = p[s0 + 9];
        ulonglong2 L0 = p[s0 - 8],     L1 = p[s0 - 7];
        unsigned long long a0 = mul2(wx, U0.x); ffma2(a0, wy, D0.x); ffma2(a0, wz, R0.x); ffma2(a0, wwv, L0.x);
        unsigned long long a1 = mul2(wx, U0.y); ffma2(a1, wy, D0.y); ffma2(a1, wz, R0.y); ffma2(a1, wwv, L0.y);
        unsigned long long a2 = mul2(wx, U1.x); ffma2(a2, wy, D1.x); ffma2(a2, wz, R1.x); ffma2(a2, wwv, L1.x);
        unsigned long long a3 = mul2(wx, U1.y); ffma2(a3, wy, D1.y); ffma2(a3, wz, R1.y); ffma2(a3, wwv, L1.y);
        float2 q0 = unpack2(a0), q1 = unpack2(a1), q2 = unpack2(a2), q3 = unpack2(a3);
        float e0 = ex2(q0.x), e1 = ex2(q0.y), e2 = ex2(q1.x), e3 = ex2(q1.y);
        float e4 = ex2(q2.x), e5 = ex2(q2.y), e6 = ex2(q3.x), e7 = ex2(q3.y);
        float s = ((e0+e1)+(e2+e3)) + ((e4+e5)+(e6+e7));
        s += __shfl_xor_sync(0xffffffffu, s, 1);
        s += __shfl_xor_sync(0xffffffffu, s, 2);
        float inv = __fdividef(1.f, s);
        unsigned long long inv2 = pack2(inv, inv);
        if (valid) {
            ulonglong2* dst = (ulonglong2*)sB + s0;
            dst[0] = make_ulonglong2(mul2(pack2(e0,e1), inv2), mul2(pack2(e2,e3), inv2));
            dst[1] = make_ulonglong2(mul2(pack2(e4,e5), inv2), mul2(pack2(e6,e7), inv2));
        }
    }
    __syncthreads();

    // ---- pass 1: 16x16 interior (offset 2), sB -> gmem. 1024 tasks, 4 iters.
    #pragma unroll
    for (int it = 0; it < 4; it++) {
        int i = tid + it*256;
        int px16 = i >> 2, kq = i & 3;
        int ly = px16 >> 4, lx = px16 & 15;
        int pc = (2 + ly)*TS + (2 + lx);
        float4 wd = s_aff[pc];
        unsigned long long wx = pack2(wd.x, wd.x), wy = pack2(wd.y, wd.y);
        unsigned long long wz = pack2(wd.z, wd.z), wwv = pack2(wd.w, wd.w);
        const ulonglong2* p = (const ulonglong2*)sB;
        int s0 = pc*8 + kq*2;
        ulonglong2 U0 = p[s0 + 8*TS],  U1 = p[s0 + 8*TS + 1];
        ulonglong2 D0 = p[s0 - 8*TS],  D1 = p[s0 - 8*TS + 1];
        ulonglong2 R0 = p[s0 + 8],     R1 = p[s0 + 9];
        ulonglong2 L0 = p[s0 - 8],     L1 = p[s0 - 7];
        unsigned long long a0 = mul2(wx, U0.x); ffma2(a0, wy, D0.x); ffma2(a0, wz, R0.x); ffma2(a0, wwv, L0.x);
        unsigned long long a1 = mul2(wx, U0.y); ffma2(a1, wy, D0.y); ffma2(a1, wz, R0.y); ffma2(a1, wwv, L0.y);
        unsigned long long a2 = mul2(wx, U1.x); ffma2(a2, wy, D1.x); ffma2(a2, wz, R1.x); ffma2(a2, wwv, L1.x);
        unsigned long long a3 = mul2(wx, U1.y); ffma2(a3, wy, D1.y); ffma2(a3, wz, R1.y); ffma2(a3, wwv, L1.y);
        float2 q0 = unpack2(a0), q1 = unpack2(a1), q2 = unpack2(a2), q3 = unpack2(a3);
        float e0 = ex2(q0.x), e1 = ex2(q0.y), e2 = ex2(q1.x), e3 = ex2(q1.y);
        float e4 = ex2(q2.x), e5 = ex2(q2.y), e6 = ex2(q3.x), e7 = ex2(q3.y);
        float s = ((e0+e1)+(e2+e3)) + ((e4+e5)+(e6+e7));
        s += __shfl_xor_sync(0xffffffffu, s, 1);
        s += __shfl_xor_sync(0xffffffffu, s, 2);
        float inv = __fdividef(1.f, s);
        unsigned long long inv2 = pack2(inv, inv);
        int gh = g0h + 2 + ly, gw = g0w + 2 + lx;
        ulonglong2* dst = (ulonglong2*)(Aout + (size_t)((b*Hv + gh)*Wv + gw)*Kv + kq*8);
        dst[0] = make_ulonglong2(mul2(pack2(e0,e1), inv2), mul2(pack2(e2,e3), inv2));
        dst[1] = make_ulonglong2(mul2(pack2(e4,e5), inv2), mul2(pack2(e6,e7), inv2));
    }
}

// ============================================================================
// pooling stage 1
// ============================================================================
__global__ __launch_bounds__(256) void pool1_kernel(
    const float* __restrict__ A, const int* __restrict__ X, float* __restrict__ part)
{
    __shared__ int   s_x[Wv];
    __shared__ float s_red[3][8][Kv];
    __shared__ float s_cls[8][Kv][Cv];

    int bh = blockIdx.x; int b = bh >> 7, h = bh & 127;
    int tid = threadIdx.x;
    int k = tid & 31, wl = tid >> 5;

    if (tid < Wv) s_x[tid] = X[(b*Hv + h)*Wv + tid];
    __syncthreads();

    float mass = 0.f, wa = 0.f, w2a = 0.f;
    float cls[Cv];
    #pragma unroll
    for (int c = 0; c < Cv; c++) cls[c] = 0.f;

    #pragma unroll 1
    for (int it = 0; it < 16; it++) {
        int w = wl*16 + it;
        float a = A[((size_t)(b*Hv + h)*Wv + w)*Kv + k];
        float fw = (w + 0.5f) * (1.f/128.f);
        mass += a;
        wa  = fmaf(a, fw, wa);
        w2a = fmaf(a, fw*fw, w2a);
        int c = s_x[w];
        #pragma unroll
        for (int cc = 0; cc < Cv; cc++) cls[cc] += (c == cc) ? a : 0.f;
    }
    s_red[0][wl][k] = mass; s_red[1][wl][k] = wa; s_red[2][wl][k] = w2a;
    #pragma unroll
    for (int cc = 0; cc < Cv; cc++) s_cls[wl][k][cc] = cls[cc];
    __syncthreads();

    if (tid < Kv) {
        float m = 0.f, a1 = 0.f, a2 = 0.f, c10[Cv];
        #pragma unroll
        for (int cc = 0; cc < Cv; cc++) c10[cc] = 0.f;
        #pragma unroll
        for (int j = 0; j < 8; j++) {
            m  += s_red[0][j][tid];
            a1 += s_red[1][j][tid];
            a2 += s_red[2][j][tid];
            #pragma unroll
            for (int cc = 0; cc < Cv; cc++) c10[cc] += s_cls[j][tid][cc];
        }
        float* dst = part + ((size_t)(b*Hv + h)*Kv + tid)*13;
        dst[0] = m; dst[1] = a1; dst[2] = a2;
        #pragma unroll
        for (int cc = 0; cc < Cv; cc++) dst[3+cc] = c10[cc];
    }
}

// ============================================================================
// pooling stage 2: block per (b,k)
// ============================================================================
__global__ __launch_bounds__(128) void pool2_kernel(
    const float* __restrict__ part, float* __restrict__ T)
{
    __shared__ float red[4][15];
    int bk = blockIdx.x;
    int b = bk >> 5, k = bk & 31;
    int h = threadIdx.x;
    int lane = h & 31, wrp = h >> 5;

    const float* p = part + ((size_t)(b*Hv + h)*Kv + k)*13;
    float m = p[0];
    float fh = (h + 0.5f) * (1.f/128.f);
    float v[15];
    v[0] = m; v[1] = m*fh; v[2] = m*fh*fh; v[3] = p[1]; v[4] = p[2];
    #pragma unroll
    for (int cc = 0; cc < Cv; cc++) v[5+cc] = p[3+cc];

    #pragma unroll
    for (int o = 16; o > 0; o >>= 1) {
        #pragma unroll
        for (int j = 0; j < 15; j++) v[j] += __shfl_xor_sync(0xffffffffu, v[j], o);
    }
    if (lane == 0) {
        #pragma unroll
        for (int j = 0; j < 15; j++) red[wrp][j] = v[j];
    }
    __syncthreads();
    if (h == 0) {
        float r[15];
        #pragma unroll
        for (int j = 0; j < 15; j++)
            r[j] = (red[0][j] + red[1][j]) + (red[2][j] + red[3][j]);
        float mass = r[0] + 1e-6f;
        float inv = 1.f / mass;
        float h_c = r[1]*inv, w_c = r[3]*inv;
        float h2 = r[2]*inv,  w2 = r[4]*inv;
        float h_sd = sqrtf(fmaxf(h2 - h_c*h_c, 0.f) + 1e-6f);
        float w_sd = sqrtf(fmaxf(w2 - w_c*w_c, 0.f) + 1e-6f);

        float* t = T + (size_t)(b*Kv + k) * T_FEATS;
        t[0] = mass * (1.f/16384.f);
        t[1] = h_c; t[2] = w_c;
        #pragma unroll
        for (int cc = 0; cc < Cv; cc++) t[3+cc] = r[5+cc]*inv;
        t[13] = h_c - h_sd; t[14] = h_c + h_sd;
        t[15] = w_c - w_sd; t[16] = w_c + w_sd;
    }
}

// ============================================================================
// launch
// ============================================================================
extern "C" void kernel_launch(void* const* d_in, const int* in_sizes, int n_in,
                              void* d_out, int out_size)
{
    const int*   X  = (const int*)  d_in[0];
    const float* w1 = (const float*)d_in[1];
    const float* b1 = (const float*)d_in[2];
    const float* w2 = (const float*)d_in[3];
    const float* b2 = (const float*)d_in[4];
    const float* w3 = (const float*)d_in[5];
    const float* b3 = (const float*)d_in[6];

    float* outA = (float*)d_out;
    float* outT = (float*)d_out + A_ELEMS;

    float *r1, *phi, *aff, *A0, *part;
    cudaGetSymbolAddress((void**)&r1,   g_r1);
    cudaGetSymbolAddress((void**)&phi,  g_phi);
    cudaGetSymbolAddress((void**)&aff,  g_aff);
    cudaGetSymbolAddress((void**)&A0,   g_A0);
    cudaGetSymbolAddress((void**)&part, g_part);

    cudaFuncSetAttribute(conv123_kernel,     cudaFuncAttributeMaxDynamicSharedMemorySize, CONV_SMEM);
    cudaFuncSetAttribute(msgpass2_ls_kernel, cudaFuncAttributeMaxDynamicSharedMemorySize, MP2LS_SMEM);

    initA_kernel<<<Hv, 128>>>(A0);                                            // 0
    conv123_kernel<<<dim3(Bv, Hv/16, Wv/16), 256, CONV_SMEM>>>(
        X, w1, b1, w2, b2, w3, b3, phi);                                      // 1
    int G = Bv*Hv*4;
    aff_ls_kernel<<<G, 128>>>(phi, aff);                                      // 2

    // 8 message passes = 4 fused-by-2 launches
    int BS = Hv*Wv*Kv;
    dim3 mpg(Wv/16, Hv/16, Bv);
    msgpass2_ls_kernel<<<mpg, 256, MP2LS_SMEM>>>(A0,  0,  aff, r1);           // 3
    msgpass2_ls_kernel<<<mpg, 256, MP2LS_SMEM>>>(r1,  BS, aff, phi);          // 4
    msgpass2_ls_kernel<<<mpg, 256, MP2LS_SMEM>>>(phi, BS, aff, r1);           // 5 <- ncu
    msgpass2_ls_kernel<<<mpg, 256, MP2LS_SMEM>>>(r1,  BS, aff, outA);         // 6

    pool1_kernel<<<Bv*Hv, 256>>>(outA, X, part);                              // 7
    pool2_kernel<<<Bv*Kv, 128>>>(part, outT);                                 // 8
}

// round 14
// speedup vs baseline: 1.3055x; 1.3055x over previous
#include <cuda_runtime.h>
#include <cuda_bf16.h>
#include <math.h>

#define Bv 32
#define Hv 128
#define Wv 128
#define Cv 10
#define Kv 32
#define CH 32

#define A_ELEMS (Bv*Hv*Wv*Kv)
#define T_FEATS 17

// -------------------- scratch --------------------
__device__ __align__(256) float g_r1 [Bv*Hv*Wv*CH];
__device__ __align__(256) float g_phi[Bv*Hv*Wv*CH];
__device__ __align__(256) float g_aff[Bv*Hv*Wv*4];
__device__ __align__(256) float g_A0 [Hv*Wv*Kv];
__device__ __align__(256) float g_part[Bv*Hv*Kv*13];

// -------------------- f32x2 helpers --------------------
__device__ __forceinline__ unsigned long long pack2(float lo, float hi) {
    unsigned long long r;
    asm("mov.b64 %0,{%1,%2};" : "=l"(r) : "f"(lo), "f"(hi));
    return r;
}
__device__ __forceinline__ float2 unpack2(unsigned long long v) {
    float2 r;
    asm("mov.b64 {%0,%1},%2;" : "=f"(r.x), "=f"(r.y) : "l"(v));
    return r;
}
__device__ __forceinline__ void ffma2(unsigned long long &d,
                                      unsigned long long a, unsigned long long b) {
    asm("fma.rn.f32x2 %0, %1, %2, %0;" : "+l"(d) : "l"(a), "l"(b));
}
__device__ __forceinline__ unsigned long long fma2o(unsigned long long a,
                                                    unsigned long long b,
                                                    unsigned long long c) {
    unsigned long long r;
    asm("fma.rn.f32x2 %0, %1, %2, %3;" : "=l"(r) : "l"(a), "l"(b), "l"(c));
    return r;
}
__device__ __forceinline__ unsigned long long mul2(unsigned long long a, unsigned long long b) {
    unsigned long long r;
    asm("mul.rn.f32x2 %0, %1, %2;" : "=l"(r) : "l"(a), "l"(b));
    return r;
}
__device__ __forceinline__ float ex2(float x) {
    float r;
    asm("ex2.approx.ftz.f32 %0, %1;" : "=f"(r) : "f"(x));
    return r;
}

// ============================================================================
// init A0
// ============================================================================
__global__ __launch_bounds__(128) void initA_kernel(float* __restrict__ A0)
{
    int h = blockIdx.x, w = threadIdx.x;
    float fh = (float)h, fw = (float)w;
    float lg[Kv]; float m = -1e30f;
    #pragma unroll
    for (int k = 0; k < Kv; k++) {
        float sh = ((k >> 3) + 0.5f) * 32.f;
        float sw = ((k & 7)  + 0.5f) * 16.f;
        float dh = fh - sh, dw = fw - sw;
        lg[k] = -(dh*dh + dw*dw) * (1.f/512.f);
        m = fmaxf(m, lg[k]);
    }
    float s = 0.f;
    #pragma unroll
    for (int k = 0; k < Kv; k++) { lg[k] = __expf(lg[k] - m); s += lg[k]; }
    float inv = 1.f / s;
    float4* dst = (float4*)(A0 + (size_t)(h*Wv + w)*Kv);
    #pragma unroll
    for (int g = 0; g < 8; g++)
        dst[g] = make_float4(lg[4*g]*inv, lg[4*g+1]*inv, lg[4*g+2]*inv, lg[4*g+3]*inv);
}

// ============================================================================
// fused conv1+conv2+conv3 -> phi  (R9 best-measured variant)
// 256 threads/block, thread = 2 strided pixels x 16 output channels.
// ============================================================================
#define R1PITCH 343
#define Y2PITCH 257
#define OFF_W1  0
#define OFF_B1  (OFF_W1 + 9*Cv*CH)
#define OFF_W2  (OFF_B1 + 32)
#define OFF_W3  (OFF_W2 + 9*CH*CH)
#define OFF_B2  (OFF_W3 + CH*CH)
#define OFF_B3  (OFF_B2 + 32)
#define OFF_X   (OFF_B3 + 32)
#define OFF_R1  (OFF_X + 400)
#define CONV_F  (OFF_R1 + CH*R1PITCH)
#define CONV_SMEM (CONV_F * 4)

__global__ __launch_bounds__(256, 2) void conv123_kernel(
    const int* __restrict__ X,
    const float* __restrict__ w1, const float* __restrict__ b1,
    const float* __restrict__ w2, const float* __restrict__ b2,
    const float* __restrict__ w3, const float* __restrict__ b3,
    float* __restrict__ phi)
{
    extern __shared__ float smem[];
    float* s_w1 = smem + OFF_W1;
    float* s_b1 = smem + OFF_B1;
    float* s_w2 = smem + OFF_W2;
    float* s_w3 = smem + OFF_W3;
    float* s_b2 = smem + OFF_B2;
    float* s_b3 = smem + OFF_B3;
    int*   s_x  = (int*)(smem + OFF_X);
    float* s_r1 = smem + OFF_R1;
    float* s_y2 = smem + OFF_R1;

    int b = blockIdx.x, h0 = blockIdx.y*16, w0 = blockIdx.z*16;
    int tid = threadIdx.x;

    for (int i = tid; i < 9*Cv*CH; i += 256) s_w1[i] = w1[i];
    for (int i = tid; i < 9*CH*CH; i += 256) s_w2[i] = w2[i];
    for (int i = tid; i < CH*CH;   i += 256) s_w3[i] = w3[i];
    if (tid < 32) { s_b1[tid] = b1[tid]; s_b2[tid] = b2[tid]; s_b3[tid] = b3[tid]; }

    for (int p = tid; p < 400; p += 256) {
        int ly = p / 20, lx = p % 20;
        int gh = h0 + ly - 2, gw = w0 + lx - 2;
        s_x[p] = (gh >= 0 && gh < Hv && gw >= 0 && gw < Wv) ? X[(b*Hv+gh)*Wv+gw] : -1;
    }
    __syncthreads();

    // ---- phase 1: r1 on 18x18 (one-hot lookup conv) ----
    {
        int co = tid & 31, wg = tid >> 5;
        for (int p = wg; p < 18*18; p += 8) {
            int lh = p / 18, lw = p % 18;
            float acc1 = s_b1[co];
            #pragma unroll
            for (int dy = 0; dy < 3; dy++) {
                #pragma unroll
                for (int dx = 0; dx < 3; dx++) {
                    int c = s_x[(lh+dy)*20 + (lw+dx)];
                    if (c >= 0) acc1 += s_w1[((dy*3+dx)*Cv + c)*CH + co];
                }
            }
            s_r1[co*R1PITCH + lh*19 + lw] = fmaxf(acc1, 0.f);
        }
    }
    __syncthreads();

    // ---- phase 2: conv2, thread = 2 strided px x 16 co ----
    int co_half = tid >> 7;
    int pg = tid & 127;
    int px0 = pg, px1 = pg + 128;
    int plh0 = px0 >> 4, plw0 = px0 & 15;
    int plh1 = px1 >> 4, plw1 = px1 & 15;
    int off0 = plh0*19 + plw0, off1 = plh1*19 + plw1;

    unsigned long long acc[16];
    #pragma unroll
    for (int j = 0; j < 2; j++)
        #pragma unroll
        for (int g = 0; g < 8; g++)
            acc[j*8+g] = pack2(s_b2[co_half*16+2*g], s_b2[co_half*16+2*g+1]);

    #pragma unroll
    for (int pos = 0; pos < 9; pos++) {
        int dy = pos / 3, dx = pos % 3;
        const float* ibase = s_r1 + dy*19 + dx;
        #pragma unroll 4
        for (int ci = 0; ci < CH; ci++) {
            const float* ib = ibase + ci*R1PITCH;
            float v0 = ib[off0];
            float v1 = ib[off1];
            const ulonglong2* wp = (const ulonglong2*)(s_w2 + pos*CH*CH + ci*CH + co_half*16);
            ulonglong2 wA = wp[0], wB = wp[1], wC = wp[2], wD = wp[3];
            unsigned long long vv0 = pack2(v0,v0), vv1 = pack2(v1,v1);
            ffma2(acc[0], vv0, wA.x); ffma2(acc[1], vv0, wA.y);
            ffma2(acc[2], vv0, wB.x); ffma2(acc[3], vv0, wB.y);
            ffma2(acc[4], vv0, wC.x); ffma2(acc[5], vv0, wC.y);
            ffma2(acc[6], vv0, wD.x); ffma2(acc[7], vv0, wD.y);
            ffma2(acc[8],  vv1, wA.x); ffma2(acc[9],  vv1, wA.y);
            ffma2(acc[10], vv1, wB.x); ffma2(acc[11], vv1, wB.y);
            ffma2(acc[12], vv1, wC.x); ffma2(acc[13], vv1, wC.y);
            ffma2(acc[14], vv1, wD.x); ffma2(acc[15], vv1, wD.y);
        }
    }
    __syncthreads();

    // relu -> s_y2 [ci][px]
    #pragma unroll
    for (int g = 0; g < 8; g++) {
        float2 v0 = unpack2(acc[g]);
        float2 v1 = unpack2(acc[8+g]);
        s_y2[(co_half*16 + 2*g  )*Y2PITCH + px0] = fmaxf(v0.x, 0.f);
        s_y2[(co_half*16 + 2*g+1)*Y2PITCH + px0] = fmaxf(v0.y, 0.f);
        s_y2[(co_half*16 + 2*g  )*Y2PITCH + px1] = fmaxf(v1.x, 0.f);
        s_y2[(co_half*16 + 2*g+1)*Y2PITCH + px1] = fmaxf(v1.y, 0.f);
    }
    __syncthreads();

    // ---- phase 3: conv3 (1x1), same accumulator array reused ----
    #pragma unroll
    for (int j = 0; j < 2; j++)
        #pragma unroll
        for (int g = 0; g < 8; g++)
            acc[j*8+g] = pack2(s_b3[co_half*16+2*g], s_b3[co_half*16+2*g+1]);

    #pragma unroll 4
    for (int ci = 0; ci < CH; ci++) {
        const float* ib = s_y2 + ci*Y2PITCH;
        float v0 = ib[px0], v1 = ib[px1];
        const ulonglong2* wp = (const ulonglong2*)(s_w3 + ci*CH + co_half*16);
        ulonglong2 wA = wp[0], wB = wp[1], wC = wp[2], wD = wp[3];
        unsigned long long vv0 = pack2(v0,v0), vv1 = pack2(v1,v1);
        ffma2(acc[0], vv0, wA.x); ffma2(acc[1], vv0, wA.y);
        ffma2(acc[2], vv0, wB.x); ffma2(acc[3], vv0, wB.y);
        ffma2(acc[4], vv0, wC.x); ffma2(acc[5], vv0, wC.y);
        ffma2(acc[6], vv0, wD.x); ffma2(acc[7], vv0, wD.y);
        ffma2(acc[8],  vv1, wA.x); ffma2(acc[9],  vv1, wA.y);
        ffma2(acc[10], vv1, wB.x); ffma2(acc[11], vv1, wB.y);
        ffma2(acc[12], vv1, wC.x); ffma2(acc[13], vv1, wC.y);
        ffma2(acc[14], vv1, wD.x); ffma2(acc[15], vv1, wD.y);
    }

    {
        float* dp0 = phi + (size_t)((b*Hv + h0+plh0)*Wv + w0+plw0)*CH + co_half*16;
        float* dp1 = phi + (size_t)((b*Hv + h0+plh1)*Wv + w0+plw1)*CH + co_half*16;
        float4* d40 = (float4*)dp0;
        float4* d41 = (float4*)dp1;
        #pragma unroll
        for (int g = 0; g < 4; g++) {
            float2 lo0 = unpack2(acc[2*g]);
            float2 hi0 = unpack2(acc[2*g+1]);
            d40[g] = make_float4(lo0.x, lo0.y, hi0.x, hi0.y);
            float2 lo1 = unpack2(acc[8+2*g]);
            float2 hi1 = unpack2(acc[8+2*g+1]);
            d41[g] = make_float4(lo1.x, lo1.y, hi1.x, hi1.y);
        }
    }
}

// ============================================================================
// lane-split neighbor affinity: 4 lanes/pixel (8 channels each), warp = 8 px.
// ============================================================================
#define AFF_SCALE 2.88539008177792681f   // 2 * log2(e)

__global__ __launch_bounds__(128, 8) void aff_ls_kernel(
    const float* __restrict__ phi, float* __restrict__ aff)
{
    int tid = threadIdx.x, lane = tid & 31, wrp = tid >> 5;
    int kq = lane & 3, pig = lane >> 2;
    int bidx = blockIdx.x;
    int wc = bidx & 3, h = (bidx >> 2) & 127, b = bidx >> 9;
    int w = wc*32 + wrp*8 + pig;
    size_t pix = (size_t)(b*Hv + h)*Wv + w;
    size_t rowb = pix*CH + kq*8;

    const ulonglong2* pc = (const ulonglong2*)(phi + rowb);
    ulonglong2 c0 = pc[0], c1 = pc[1];
    unsigned long long M1 = pack2(-1.f, -1.f);

    long offs[4];
    offs[0] = (h+1 < Hv) ? (long)Wv*CH : 0;
    offs[1] = (h   >= 1) ? -(long)Wv*CH : 0;
    offs[2] = (w+1 < Wv) ? (long)CH : 0;
    offs[3] = (w   >= 1) ? -(long)CH : 0;

    float s[4];
    #pragma unroll
    for (int d = 0; d < 4; d++) {
        const ulonglong2* pn = (const ulonglong2*)(phi + rowb + offs[d]);
        ulonglong2 n0 = pn[0], n1 = pn[1];
        unsigned long long a = pack2(0.f, 0.f);
        unsigned long long t0 = fma2o(n0.x, M1, c0.x); a = fma2o(t0, t0, a);
        unsigned long long t1 = fma2o(n0.y, M1, c0.y); a = fma2o(t1, t1, a);
        unsigned long long t2 = fma2o(n1.x, M1, c1.x); a = fma2o(t2, t2, a);
        unsigned long long t3 = fma2o(n1.y, M1, c1.y); a = fma2o(t3, t3, a);
        float2 p = unpack2(a);
        s[d] = p.x + p.y;
    }
    #pragma unroll
    for (int d = 0; d < 4; d++) {
        s[d] += __shfl_xor_sync(0xffffffffu, s[d], 1);
        s[d] += __shfl_xor_sync(0xffffffffu, s[d], 2);
    }
    if (kq == 0) {
        float4 wd;
        wd.x = (h+1 < Hv) ? AFF_SCALE * __expf(-2.f*s[0]) : 0.f;
        wd.y = (h   >= 1) ? AFF_SCALE * __expf(-2.f*s[1]) : 0.f;
        wd.z = (w+1 < Wv) ? AFF_SCALE * __expf(-2.f*s[2]) : 0.f;
        wd.w = (w   >= 1) ? AFF_SCALE * __expf(-2.f*s[3]) : 0.f;
        ((float4*)aff)[pix] = wd;
    }
}

// ============================================================================
// lane-split message pass: 4 lanes/pixel, warp = 8 px, coalesced loads.
// ============================================================================
__global__ __launch_bounds__(128, 8) void msgpass_ls_kernel(
    const float* __restrict__ Ain, int bstride,
    const float* __restrict__ aff, float* __restrict__ Aout)
{
    int tid = threadIdx.x, lane = tid & 31, wrp = tid >> 5;
    int kq = lane & 3, pig = lane >> 2;
    int bidx = blockIdx.x;
    int wc = bidx & 3, h = (bidx >> 2) & 127, b = bidx >> 9;
    int w = wc*32 + wrp*8 + pig;
    size_t pix = (size_t)(b*Hv + h)*Wv + w;

    float4 wd = ((const float4*)aff)[pix];
    unsigned long long wx = pack2(wd.x, wd.x), wy = pack2(wd.y, wd.y);
    unsigned long long wz = pack2(wd.z, wd.z), wwv = pack2(wd.w, wd.w);

    const float* base = Ain + (size_t)b * bstride;
    size_t loc = (size_t)h*Wv + w;
    size_t locU = (h+1 < Hv) ? loc + Wv : loc;
    size_t locD = (h   >= 1) ? loc - Wv : loc;
    size_t locR = (w+1 < Wv) ? loc + 1  : loc;
    size_t locL = (w   >= 1) ? loc - 1  : loc;
    int ko = kq*8;
    const ulonglong2* pU = (const ulonglong2*)(base + locU*Kv + ko);
    const ulonglong2* pD = (const ulonglong2*)(base + locD*Kv + ko);
    const ulonglong2* pR = (const ulonglong2*)(base + locR*Kv + ko);
    const ulonglong2* pL = (const ulonglong2*)(base + locL*Kv + ko);

    ulonglong2 U0 = pU[0], U1 = pU[1];
    ulonglong2 D0 = pD[0], D1 = pD[1];
    ulonglong2 R0 = pR[0], R1 = pR[1];
    ulonglong2 L0 = pL[0], L1 = pL[1];

    unsigned long long a0 = mul2(wx, U0.x); ffma2(a0, wy, D0.x); ffma2(a0, wz, R0.x); ffma2(a0, wwv, L0.x);
    unsigned long long a1 = mul2(wx, U0.y); ffma2(a1, wy, D0.y); ffma2(a1, wz, R0.y); ffma2(a1, wwv, L0.y);
    unsigned long long a2 = mul2(wx, U1.x); ffma2(a2, wy, D1.x); ffma2(a2, wz, R1.x); ffma2(a2, wwv, L1.x);
    unsigned long long a3 = mul2(wx, U1.y); ffma2(a3, wy, D1.y); ffma2(a3, wz, R1.y); ffma2(a3, wwv, L1.y);

    float2 q0 = unpack2(a0), q1 = unpack2(a1), q2 = unpack2(a2), q3 = unpack2(a3);
    float e0 = ex2(q0.x), e1 = ex2(q0.y), e2 = ex2(q1.x), e3 = ex2(q1.y);
    float e4 = ex2(q2.x), e5 = ex2(q2.y), e6 = ex2(q3.x), e7 = ex2(q3.y);
    float s = ((e0+e1)+(e2+e3)) + ((e4+e5)+(e6+e7));
    s += __shfl_xor_sync(0xffffffffu, s, 1);
    s += __shfl_xor_sync(0xffffffffu, s, 2);
    float inv = __fdividef(1.f, s);
    unsigned long long inv2 = pack2(inv, inv);

    ulonglong2* dst = (ulonglong2*)(Aout + pix*Kv + ko);
    dst[0] = make_ulonglong2(mul2(pack2(e0,e1), inv2), mul2(pack2(e2,e3), inv2));
    dst[1] = make_ulonglong2(mul2(pack2(e4,e5), inv2), mul2(pack2(e6,e7), inv2));
}

// ============================================================================
// pooling stage 1
// ============================================================================
__global__ __launch_bounds__(256) void pool1_kernel(
    const float* __restrict__ A, const int* __restrict__ X, float* __restrict__ part)
{
    __shared__ int   s_x[Wv];
    __shared__ float s_red[3][8][Kv];
    __shared__ float s_cls[8][Kv][Cv];

    int bh = blockIdx.x; int b = bh >> 7, h = bh & 127;
    int tid = threadIdx.x;
    int k = tid & 31, wl = tid >> 5;

    if (tid < Wv) s_x[tid] = X[(b*Hv + h)*Wv + tid];
    __syncthreads();

    float mass = 0.f, wa = 0.f, w2a = 0.f;
    float cls[Cv];
    #pragma unroll
    for (int c = 0; c < Cv; c++) cls[c] = 0.f;

    #pragma unroll 1
    for (int it = 0; it < 16; it++) {
        int w = wl*16 + it;
        float a = A[((size_t)(b*Hv + h)*Wv + w)*Kv + k];
        float fw = (w + 0.5f) * (1.f/128.f);
        mass += a;
        wa  = fmaf(a, fw, wa);
        w2a = fmaf(a, fw*fw, w2a);
        int c = s_x[w];
        #pragma unroll
        for (int cc = 0; cc < Cv; cc++) cls[cc] += (c == cc) ? a : 0.f;
    }
    s_red[0][wl][k] = mass; s_red[1][wl][k] = wa; s_red[2][wl][k] = w2a;
    #pragma unroll
    for (int cc = 0; cc < Cv; cc++) s_cls[wl][k][cc] = cls[cc];
    __syncthreads();

    if (tid < Kv) {
        float m = 0.f, a1 = 0.f, a2 = 0.f, c10[Cv];
        #pragma unroll
        for (int cc = 0; cc < Cv; cc++) c10[cc] = 0.f;
        #pragma unroll
        for (int j = 0; j < 8; j++) {
            m  += s_red[0][j][tid];
            a1 += s_red[1][j][tid];
            a2 += s_red[2][j][tid];
            #pragma unroll
            for (int cc = 0; cc < Cv; cc++) c10[cc] += s_cls[j][tid][cc];
        }
        float* dst = part + ((size_t)(b*Hv + h)*Kv + tid)*13;
        dst[0] = m; dst[1] = a1; dst[2] = a2;
        #pragma unroll
        for (int cc = 0; cc < Cv; cc++) dst[3+cc] = c10[cc];
    }
}

// ============================================================================
// pooling stage 2: block per (b,k)
// ============================================================================
__global__ __launch_bounds__(128) void pool2_kernel(
    const float* __restrict__ part, float* __restrict__ T)
{
    __shared__ float red[4][15];
    int bk = blockIdx.x;
    int b = bk >> 5, k = bk & 31;
    int h = threadIdx.x;
    int lane = h & 31, wrp = h >> 5;

    const float* p = part + ((size_t)(b*Hv + h)*Kv + k)*13;
    float m = p[0];
    float fh = (h + 0.5f) * (1.f/128.f);
    float v[15];
    v[0] = m; v[1] = m*fh; v[2] = m*fh*fh; v[3] = p[1]; v[4] = p[2];
    #pragma unroll
    for (int cc = 0; cc < Cv; cc++) v[5+cc] = p[3+cc];

    #pragma unroll
    for (int o = 16; o > 0; o >>= 1) {
        #pragma unroll
        for (int j = 0; j < 15; j++) v[j] += __shfl_xor_sync(0xffffffffu, v[j], o);
    }
    if (lane == 0) {
        #pragma unroll
        for (int j = 0; j < 15; j++) red[wrp][j] = v[j];
    }
    __syncthreads();
    if (h == 0) {
        float r[15];
        #pragma unroll
        for (int j = 0; j < 15; j++)
            r[j] = (red[0][j] + red[1][j]) + (red[2][j] + red[3][j]);
        float mass = r[0] + 1e-6f;
        float inv = 1.f / mass;
        float h_c = r[1]*inv, w_c = r[3]*inv;
        float h2 = r[2]*inv,  w2 = r[4]*inv;
        float h_sd = sqrtf(fmaxf(h2 - h_c*h_c, 0.f) + 1e-6f);
        float w_sd = sqrtf(fmaxf(w2 - w_c*w_c, 0.f) + 1e-6f);

        float* t = T + (size_t)(b*Kv + k) * T_FEATS;
        t[0] = mass * (1.f/16384.f);
        t[1] = h_c; t[2] = w_c;
        #pragma unroll
        for (int cc = 0; cc < Cv; cc++) t[3+cc] = r[5+cc]*inv;
        t[13] = h_c - h_sd; t[14] = h_c + h_sd;
        t[15] = w_c - w_sd; t[16] = w_c + w_sd;
    }
}

// ============================================================================
// launch
// ============================================================================
extern "C" void kernel_launch(void* const* d_in, const int* in_sizes, int n_in,
                              void* d_out, int out_size)
{
    const int*   X  = (const int*)  d_in[0];
    const float* w1 = (const float*)d_in[1];
    const float* b1 = (const float*)d_in[2];
    const float* w2 = (const float*)d_in[3];
    const float* b2 = (const float*)d_in[4];
    const float* w3 = (const float*)d_in[5];
    const float* b3 = (const float*)d_in[6];

    float* outA = (float*)d_out;
    float* outT = (float*)d_out + A_ELEMS;

    float *r1, *phi, *aff, *A0, *part;
    cudaGetSymbolAddress((void**)&r1,   g_r1);
    cudaGetSymbolAddress((void**)&phi,  g_phi);
    cudaGetSymbolAddress((void**)&aff,  g_aff);
    cudaGetSymbolAddress((void**)&A0,   g_A0);
    cudaGetSymbolAddress((void**)&part, g_part);

    cudaFuncSetAttribute(conv123_kernel, cudaFuncAttributeMaxDynamicSharedMemorySize, CONV_SMEM);

    initA_kernel<<<Hv, 128>>>(A0);                                            // 0
    conv123_kernel<<<dim3(Bv, Hv/16, Wv/16), 256, CONV_SMEM>>>(
        X, w1, b1, w2, b2, w3, b3, phi);                                      // 1
    int G = Bv*Hv*4;
    aff_ls_kernel<<<G, 128>>>(phi, aff);                                      // 2

    int BS = Hv*Wv*Kv;
    msgpass_ls_kernel<<<G, 128>>>(A0,  0,  aff, r1);                          // 3 <- ncu
    msgpass_ls_kernel<<<G, 128>>>(r1,  BS, aff, phi);                         // 4
    msgpass_ls_kernel<<<G, 128>>>(phi, BS, aff, r1);                          // 5
    msgpass_ls_kernel<<<G, 128>>>(r1,  BS, aff, phi);                         // 6
    msgpass_ls_kernel<<<G, 128>>>(phi, BS, aff, r1);                          // 7
    msgpass_ls_kernel<<<G, 128>>>(r1,  BS, aff, phi);                         // 8
    msgpass_ls_kernel<<<G, 128>>>(phi, BS, aff, r1);                          // 9
    msgpass_ls_kernel<<<G, 128>>>(r1,  BS, aff, outA);                        // 10

    pool1_kernel<<<Bv*Hv, 256>>>(outA, X, part);                              // 11
    pool2_kernel<<<Bv*Kv, 128>>>(part, outT);                                 // 12
}

// round 15
// speedup vs baseline: 1.3177x; 1.0094x over previous
#include <cuda_runtime.h>
#include <cuda_bf16.h>
#include <math.h>

#define Bv 32
#define Hv 128
#define Wv 128
#define Cv 10
#define Kv 32
#define CH 32

#define A_ELEMS (Bv*Hv*Wv*Kv)
#define T_FEATS 17

// -------------------- scratch --------------------
__device__ __align__(256) float g_r1 [Bv*Hv*Wv*CH];
__device__ __align__(256) float g_phi[Bv*Hv*Wv*CH];
__device__ __align__(256) float g_aff[Bv*Hv*Wv*4];
__device__ __align__(256) float g_A0 [Hv*Wv*Kv];
__device__ __align__(256) float g_part[Bv*Hv*Kv*13];

// -------------------- f32x2 helpers --------------------
__device__ __forceinline__ unsigned long long pack2(float lo, float hi) {
    unsigned long long r;
    asm("mov.b64 %0,{%1,%2};" : "=l"(r) : "f"(lo), "f"(hi));
    return r;
}
__device__ __forceinline__ float2 unpack2(unsigned long long v) {
    float2 r;
    asm("mov.b64 {%0,%1},%2;" : "=f"(r.x), "=f"(r.y) : "l"(v));
    return r;
}
__device__ __forceinline__ void ffma2(unsigned long long &d,
                                      unsigned long long a, unsigned long long b) {
    asm("fma.rn.f32x2 %0, %1, %2, %0;" : "+l"(d) : "l"(a), "l"(b));
}
__device__ __forceinline__ unsigned long long fma2o(unsigned long long a,
                                                    unsigned long long b,
                                                    unsigned long long c) {
    unsigned long long r;
    asm("fma.rn.f32x2 %0, %1, %2, %3;" : "=l"(r) : "l"(a), "l"(b), "l"(c));
    return r;
}
__device__ __forceinline__ unsigned long long mul2(unsigned long long a, unsigned long long b) {
    unsigned long long r;
    asm("mul.rn.f32x2 %0, %1, %2;" : "=l"(r) : "l"(a), "l"(b));
    return r;
}
__device__ __forceinline__ float ex2(float x) {
    float r;
    asm("ex2.approx.ftz.f32 %0, %1;" : "=f"(r) : "f"(x));
    return r;
}

// ============================================================================
// init A0
// ============================================================================
__global__ __launch_bounds__(128) void initA_kernel(float* __restrict__ A0)
{
    int h = blockIdx.x, w = threadIdx.x;
    float fh = (float)h, fw = (float)w;
    float lg[Kv]; float m = -1e30f;
    #pragma unroll
    for (int k = 0; k < Kv; k++) {
        float sh = ((k >> 3) + 0.5f) * 32.f;
        float sw = ((k & 7)  + 0.5f) * 16.f;
        float dh = fh - sh, dw = fw - sw;
        lg[k] = -(dh*dh + dw*dw) * (1.f/512.f);
        m = fmaxf(m, lg[k]);
    }
    float s = 0.f;
    #pragma unroll
    for (int k = 0; k < Kv; k++) { lg[k] = __expf(lg[k] - m); s += lg[k]; }
    float inv = 1.f / s;
    float4* dst = (float4*)(A0 + (size_t)(h*Wv + w)*Kv);
    #pragma unroll
    for (int g = 0; g < 8; g++)
        dst[g] = make_float4(lg[4*g]*inv, lg[4*g+1]*inv, lg[4*g+2]*inv, lg[4*g+3]*inv);
}

// ============================================================================
// fused conv1+conv2+conv3 -> phi  (R9 best-measured variant)
// ============================================================================
#define R1PITCH 343
#define Y2PITCH 257
#define OFF_W1  0
#define OFF_B1  (OFF_W1 + 9*Cv*CH)
#define OFF_W2  (OFF_B1 + 32)
#define OFF_W3  (OFF_W2 + 9*CH*CH)
#define OFF_B2  (OFF_W3 + CH*CH)
#define OFF_B3  (OFF_B2 + 32)
#define OFF_X   (OFF_B3 + 32)
#define OFF_R1  (OFF_X + 400)
#define CONV_F  (OFF_R1 + CH*R1PITCH)
#define CONV_SMEM (CONV_F * 4)

__global__ __launch_bounds__(256, 2) void conv123_kernel(
    const int* __restrict__ X,
    const float* __restrict__ w1, const float* __restrict__ b1,
    const float* __restrict__ w2, const float* __restrict__ b2,
    const float* __restrict__ w3, const float* __restrict__ b3,
    float* __restrict__ phi)
{
    extern __shared__ float smem[];
    float* s_w1 = smem + OFF_W1;
    float* s_b1 = smem + OFF_B1;
    float* s_w2 = smem + OFF_W2;
    float* s_w3 = smem + OFF_W3;
    float* s_b2 = smem + OFF_B2;
    float* s_b3 = smem + OFF_B3;
    int*   s_x  = (int*)(smem + OFF_X);
    float* s_r1 = smem + OFF_R1;
    float* s_y2 = smem + OFF_R1;

    int b = blockIdx.x, h0 = blockIdx.y*16, w0 = blockIdx.z*16;
    int tid = threadIdx.x;

    for (int i = tid; i < 9*Cv*CH; i += 256) s_w1[i] = w1[i];
    for (int i = tid; i < 9*CH*CH; i += 256) s_w2[i] = w2[i];
    for (int i = tid; i < CH*CH;   i += 256) s_w3[i] = w3[i];
    if (tid < 32) { s_b1[tid] = b1[tid]; s_b2[tid] = b2[tid]; s_b3[tid] = b3[tid]; }

    for (int p = tid; p < 400; p += 256) {
        int ly = p / 20, lx = p % 20;
        int gh = h0 + ly - 2, gw = w0 + lx - 2;
        s_x[p] = (gh >= 0 && gh < Hv && gw >= 0 && gw < Wv) ? X[(b*Hv+gh)*Wv+gw] : -1;
    }
    __syncthreads();

    {
        int co = tid & 31, wg = tid >> 5;
        for (int p = wg; p < 18*18; p += 8) {
            int lh = p / 18, lw = p % 18;
            float acc1 = s_b1[co];
            #pragma unroll
            for (int dy = 0; dy < 3; dy++) {
                #pragma unroll
                for (int dx = 0; dx < 3; dx++) {
                    int c = s_x[(lh+dy)*20 + (lw+dx)];
                    if (c >= 0) acc1 += s_w1[((dy*3+dx)*Cv + c)*CH + co];
                }
            }
            s_r1[co*R1PITCH + lh*19 + lw] = fmaxf(acc1, 0.f);
        }
    }
    __syncthreads();

    int co_half = tid >> 7;
    int pg = tid & 127;
    int px0 = pg, px1 = pg + 128;
    int plh0 = px0 >> 4, plw0 = px0 & 15;
    int plh1 = px1 >> 4, plw1 = px1 & 15;
    int off0 = plh0*19 + plw0, off1 = plh1*19 + plw1;

    unsigned long long acc[16];
    #pragma unroll
    for (int j = 0; j < 2; j++)
        #pragma unroll
        for (int g = 0; g < 8; g++)
            acc[j*8+g] = pack2(s_b2[co_half*16+2*g], s_b2[co_half*16+2*g+1]);

    #pragma unroll
    for (int pos = 0; pos < 9; pos++) {
        int dy = pos / 3, dx = pos % 3;
        const float* ibase = s_r1 + dy*19 + dx;
        #pragma unroll 4
        for (int ci = 0; ci < CH; ci++) {
            const float* ib = ibase + ci*R1PITCH;
            float v0 = ib[off0];
            float v1 = ib[off1];
            const ulonglong2* wp = (const ulonglong2*)(s_w2 + pos*CH*CH + ci*CH + co_half*16);
            ulonglong2 wA = wp[0], wB = wp[1], wC = wp[2], wD = wp[3];
            unsigned long long vv0 = pack2(v0,v0), vv1 = pack2(v1,v1);
            ffma2(acc[0], vv0, wA.x); ffma2(acc[1], vv0, wA.y);
            ffma2(acc[2], vv0, wB.x); ffma2(acc[3], vv0, wB.y);
            ffma2(acc[4], vv0, wC.x); ffma2(acc[5], vv0, wC.y);
            ffma2(acc[6], vv0, wD.x); ffma2(acc[7], vv0, wD.y);
            ffma2(acc[8],  vv1, wA.x); ffma2(acc[9],  vv1, wA.y);
            ffma2(acc[10], vv1, wB.x); ffma2(acc[11], vv1, wB.y);
            ffma2(acc[12], vv1, wC.x); ffma2(acc[13], vv1, wC.y);
            ffma2(acc[14], vv1, wD.x); ffma2(acc[15], vv1, wD.y);
        }
    }
    __syncthreads();

    #pragma unroll
    for (int g = 0; g < 8; g++) {
        float2 v0 = unpack2(acc[g]);
        float2 v1 = unpack2(acc[8+g]);
        s_y2[(co_half*16 + 2*g  )*Y2PITCH + px0] = fmaxf(v0.x, 0.f);
        s_y2[(co_half*16 + 2*g+1)*Y2PITCH + px0] = fmaxf(v0.y, 0.f);
        s_y2[(co_half*16 + 2*g  )*Y2PITCH + px1] = fmaxf(v1.x, 0.f);
        s_y2[(co_half*16 + 2*g+1)*Y2PITCH + px1] = fmaxf(v1.y, 0.f);
    }
    __syncthreads();

    #pragma unroll
    for (int j = 0; j < 2; j++)
        #pragma unroll
        for (int g = 0; g < 8; g++)
            acc[j*8+g] = pack2(s_b3[co_half*16+2*g], s_b3[co_half*16+2*g+1]);

    #pragma unroll 4
    for (int ci = 0; ci < CH; ci++) {
        const float* ib = s_y2 + ci*Y2PITCH;
        float v0 = ib[px0], v1 = ib[px1];
        const ulonglong2* wp = (const ulonglong2*)(s_w3 + ci*CH + co_half*16);
        ulonglong2 wA = wp[0], wB = wp[1], wC = wp[2], wD = wp[3];
        unsigned long long vv0 = pack2(v0,v0), vv1 = pack2(v1,v1);
        ffma2(acc[0], vv0, wA.x); ffma2(acc[1], vv0, wA.y);
        ffma2(acc[2], vv0, wB.x); ffma2(acc[3], vv0, wB.y);
        ffma2(acc[4], vv0, wC.x); ffma2(acc[5], vv0, wC.y);
        ffma2(acc[6], vv0, wD.x); ffma2(acc[7], vv0, wD.y);
        ffma2(acc[8],  vv1, wA.x); ffma2(acc[9],  vv1, wA.y);
        ffma2(acc[10], vv1, wB.x); ffma2(acc[11], vv1, wB.y);
        ffma2(acc[12], vv1, wC.x); ffma2(acc[13], vv1, wC.y);
        ffma2(acc[14], vv1, wD.x); ffma2(acc[15], vv1, wD.y);
    }

    {
        float* dp0 = phi + (size_t)((b*Hv + h0+plh0)*Wv + w0+plw0)*CH + co_half*16;
        float* dp1 = phi + (size_t)((b*Hv + h0+plh1)*Wv + w0+plw1)*CH + co_half*16;
        float4* d40 = (float4*)dp0;
        float4* d41 = (float4*)dp1;
        #pragma unroll
        for (int g = 0; g < 4; g++) {
            float2 lo0 = unpack2(acc[2*g]);
            float2 hi0 = unpack2(acc[2*g+1]);
            d40[g] = make_float4(lo0.x, lo0.y, hi0.x, hi0.y);
            float2 lo1 = unpack2(acc[8+2*g]);
            float2 hi1 = unpack2(acc[8+2*g+1]);
            d41[g] = make_float4(lo1.x, lo1.y, hi1.x, hi1.y);
        }
    }
}

// ============================================================================
// full-density lane-split affinity: 8 lanes/pixel (4 channels = 16B each),
// warp = 4 adjacent pixels -> every load is 512B contiguous per warp.
// ============================================================================
#define AFF_SCALE 2.88539008177792681f   // 2 * log2(e)

__global__ __launch_bounds__(128, 8) void aff_ls8_kernel(
    const float* __restrict__ phi, float* __restrict__ aff)
{
    int tid = threadIdx.x, lane = tid & 31, wrp = tid >> 5;
    int kq = lane & 7, pig = lane >> 3;         // 8 lanes/px, 4 px/warp
    int bidx = blockIdx.x;
    int wc = bidx & 7, h = (bidx >> 3) & 127, b = bidx >> 10;
    int w = wc*16 + wrp*4 + pig;
    size_t pix = (size_t)(b*Hv + h)*Wv + w;
    size_t rowb = pix*CH + kq*4;

    ulonglong2 c = *(const ulonglong2*)(phi + rowb);
    unsigned long long M1 = pack2(-1.f, -1.f);

    long offs[4];
    offs[0] = (h+1 < Hv) ? (long)Wv*CH : 0;
    offs[1] = (h   >= 1) ? -(long)Wv*CH : 0;
    offs[2] = (w+1 < Wv) ? (long)CH : 0;
    offs[3] = (w   >= 1) ? -(long)CH : 0;

    float s[4];
    #pragma unroll
    for (int d = 0; d < 4; d++) {
        ulonglong2 n = *(const ulonglong2*)(phi + rowb + offs[d]);
        unsigned long long t0 = fma2o(n.x, M1, c.x);
        unsigned long long a  = mul2(t0, t0);
        unsigned long long t1 = fma2o(n.y, M1, c.y);
        a = fma2o(t1, t1, a);
        float2 p = unpack2(a);
        s[d] = p.x + p.y;
    }
    #pragma unroll
    for (int d = 0; d < 4; d++) {
        s[d] += __shfl_xor_sync(0xffffffffu, s[d], 1);
        s[d] += __shfl_xor_sync(0xffffffffu, s[d], 2);
        s[d] += __shfl_xor_sync(0xffffffffu, s[d], 4);
    }
    if (kq == 0) {
        float4 wd;
        wd.x = (h+1 < Hv) ? AFF_SCALE * __expf(-2.f*s[0]) : 0.f;
        wd.y = (h   >= 1) ? AFF_SCALE * __expf(-2.f*s[1]) : 0.f;
        wd.z = (w+1 < Wv) ? AFF_SCALE * __expf(-2.f*s[2]) : 0.f;
        wd.w = (w   >= 1) ? AFF_SCALE * __expf(-2.f*s[3]) : 0.f;
        ((float4*)aff)[pix] = wd;
    }
}

// ============================================================================
// full-density lane-split message pass: 8 lanes/pixel (16B each),
// warp = 4 adjacent pixels. One 16B load per neighbor per lane; every
// neighbor load is a fully-dense 512B warp access (4 wavefronts).
// Softmax sum via 3 shfl over the 8-lane group.
// ============================================================================
__global__ __launch_bounds__(128, 8) void msgpass_ls8_kernel(
    const float* __restrict__ Ain, int bstride,
    const float* __restrict__ aff, float* __restrict__ Aout)
{
    int tid = threadIdx.x, lane = tid & 31, wrp = tid >> 5;
    int kq = lane & 7, pig = lane >> 3;
    int bidx = blockIdx.x;
    int wc = bidx & 7, h = (bidx >> 3) & 127, b = bidx >> 10;
    int w = wc*16 + wrp*4 + pig;
    size_t pix = (size_t)(b*Hv + h)*Wv + w;

    float4 wd = ((const float4*)aff)[pix];
    unsigned long long wx = pack2(wd.x, wd.x), wy = pack2(wd.y, wd.y);
    unsigned long long wz = pack2(wd.z, wd.z), wwv = pack2(wd.w, wd.w);

    const float* base = Ain + (size_t)b * bstride;
    size_t loc = (size_t)h*Wv + w;
    size_t locU = (h+1 < Hv) ? loc + Wv : loc;
    size_t locD = (h   >= 1) ? loc - Wv : loc;
    size_t locR = (w+1 < Wv) ? loc + 1  : loc;
    size_t locL = (w   >= 1) ? loc - 1  : loc;
    int ko = kq*4;
    ulonglong2 U = *(const ulonglong2*)(base + locU*Kv + ko);
    ulonglong2 D = *(const ulonglong2*)(base + locD*Kv + ko);
    ulonglong2 R = *(const ulonglong2*)(base + locR*Kv + ko);
    ulonglong2 L = *(const ulonglong2*)(base + locL*Kv + ko);

    unsigned long long a0 = mul2(wx, U.x);
    ffma2(a0, wy, D.x); ffma2(a0, wz, R.x); ffma2(a0, wwv, L.x);
    unsigned long long a1 = mul2(wx, U.y);
    ffma2(a1, wy, D.y); ffma2(a1, wz, R.y); ffma2(a1, wwv, L.y);

    float2 q0 = unpack2(a0), q1 = unpack2(a1);
    float e0 = ex2(q0.x), e1 = ex2(q0.y), e2 = ex2(q1.x), e3 = ex2(q1.y);
    float s = (e0 + e1) + (e2 + e3);
    s += __shfl_xor_sync(0xffffffffu, s, 1);
    s += __shfl_xor_sync(0xffffffffu, s, 2);
    s += __shfl_xor_sync(0xffffffffu, s, 4);
    float inv = __fdividef(1.f, s);
    unsigned long long inv2 = pack2(inv, inv);

    *(ulonglong2*)(Aout + pix*Kv + ko) =
        make_ulonglong2(mul2(pack2(e0,e1), inv2), mul2(pack2(e2,e3), inv2));
}

// ============================================================================
// pooling stage 1
// ============================================================================
__global__ __launch_bounds__(256) void pool1_kernel(
    const float* __restrict__ A, const int* __restrict__ X, float* __restrict__ part)
{
    __shared__ int   s_x[Wv];
    __shared__ float s_red[3][8][Kv];
    __shared__ float s_cls[8][Kv][Cv];

    int bh = blockIdx.x; int b = bh >> 7, h = bh & 127;
    int tid = threadIdx.x;
    int k = tid & 31, wl = tid >> 5;

    if (tid < Wv) s_x[tid] = X[(b*Hv + h)*Wv + tid];
    __syncthreads();

    float mass = 0.f, wa = 0.f, w2a = 0.f;
    float cls[Cv];
    #pragma unroll
    for (int c = 0; c < Cv; c++) cls[c] = 0.f;

    #pragma unroll 1
    for (int it = 0; it < 16; it++) {
        int w = wl*16 + it;
        float a = A[((size_t)(b*Hv + h)*Wv + w)*Kv + k];
        float fw = (w + 0.5f) * (1.f/128.f);
        mass += a;
        wa  = fmaf(a, fw, wa);
        w2a = fmaf(a, fw*fw, w2a);
        int c = s_x[w];
        #pragma unroll
        for (int cc = 0; cc < Cv; cc++) cls[cc] += (c == cc) ? a : 0.f;
    }
    s_red[0][wl][k] = mass; s_red[1][wl][k] = wa; s_red[2][wl][k] = w2a;
    #pragma unroll
    for (int cc = 0; cc < Cv; cc++) s_cls[wl][k][cc] = cls[cc];
    __syncthreads();

    if (tid < Kv) {
        float m = 0.f, a1 = 0.f, a2 = 0.f, c10[Cv];
        #pragma unroll
        for (int cc = 0; cc < Cv; cc++) c10[cc] = 0.f;
        #pragma unroll
        for (int j = 0; j < 8; j++) {
            m  += s_red[0][j][tid];
            a1 += s_red[1][j][tid];
            a2 += s_red[2][j][tid];
            #pragma unroll
            for (int cc = 0; cc < Cv; cc++) c10[cc] += s_cls[j][tid][cc];
        }
        float* dst = part + ((size_t)(b*Hv + h)*Kv + tid)*13;
        dst[0] = m; dst[1] = a1; dst[2] = a2;
        #pragma unroll
        for (int cc = 0; cc < Cv; cc++) dst[3+cc] = c10[cc];
    }
}

// ============================================================================
// pooling stage 2: block per (b,k)
// ============================================================================
__global__ __launch_bounds__(128) void pool2_kernel(
    const float* __restrict__ part, float* __restrict__ T)
{
    __shared__ float red[4][15];
    int bk = blockIdx.x;
    int b = bk >> 5, k = bk & 31;
    int h = threadIdx.x;
    int lane = h & 31, wrp = h >> 5;

    const float* p = part + ((size_t)(b*Hv + h)*Kv + k)*13;
    float m = p[0];
    float fh = (h + 0.5f) * (1.f/128.f);
    float v[15];
    v[0] = m; v[1] = m*fh; v[2] = m*fh*fh; v[3] = p[1]; v[4] = p[2];
    #pragma unroll
    for (int cc = 0; cc < Cv; cc++) v[5+cc] = p[3+cc];

    #pragma unroll
    for (int o = 16; o > 0; o >>= 1) {
        #pragma unroll
        for (int j = 0; j < 15; j++) v[j] += __shfl_xor_sync(0xffffffffu, v[j], o);
    }
    if (lane == 0) {
        #pragma unroll
        for (int j = 0; j < 15; j++) red[wrp][j] = v[j];
    }
    __syncthreads();
    if (h == 0) {
        float r[15];
        #pragma unroll
        for (int j = 0; j < 15; j++)
            r[j] = (red[0][j] + red[1][j]) + (red[2][j] + red[3][j]);
        float mass = r[0] + 1e-6f;
        float inv = 1.f / mass;
        float h_c = r[1]*inv, w_c = r[3]*inv;
        float h2 = r[2]*inv,  w2 = r[4]*inv;
        float h_sd = sqrtf(fmaxf(h2 - h_c*h_c, 0.f) + 1e-6f);
        float w_sd = sqrtf(fmaxf(w2 - w_c*w_c, 0.f) + 1e-6f);

        float* t = T + (size_t)(b*Kv + k) * T_FEATS;
        t[0] = mass * (1.f/16384.f);
        t[1] = h_c; t[2] = w_c;
        #pragma unroll
        for (int cc = 0; cc < Cv; cc++) t[3+cc] = r[5+cc]*inv;
        t[13] = h_c - h_sd; t[14] = h_c + h_sd;
        t[15] = w_c - w_sd; t[16] = w_c + w_sd;
    }
}

// ============================================================================
// launch
// ============================================================================
extern "C" void kernel_launch(void* const* d_in, const int* in_sizes, int n_in,
                              void* d_out, int out_size)
{
    const int*   X  = (const int*)  d_in[0];
    const float* w1 = (const float*)d_in[1];
    const float* b1 = (const float*)d_in[2];
    const float* w2 = (const float*)d_in[3];
    const float* b2 = (const float*)d_in[4];
    const float* w3 = (const float*)d_in[5];
    const float* b3 = (const float*)d_in[6];

    float* outA = (float*)d_out;
    float* outT = (float*)d_out + A_ELEMS;

    float *r1, *phi, *aff, *A0, *part;
    cudaGetSymbolAddress((void**)&r1,   g_r1);
    cudaGetSymbolAddress((void**)&phi,  g_phi);
    cudaGetSymbolAddress((void**)&aff,  g_aff);
    cudaGetSymbolAddress((void**)&A0,   g_A0);
    cudaGetSymbolAddress((void**)&part, g_part);

    cudaFuncSetAttribute(conv123_kernel, cudaFuncAttributeMaxDynamicSharedMemorySize, CONV_SMEM);

    initA_kernel<<<Hv, 128>>>(A0);                                            // 0
    conv123_kernel<<<dim3(Bv, Hv/16, Wv/16), 256, CONV_SMEM>>>(
        X, w1, b1, w2, b2, w3, b3, phi);                                      // 1
    int G8 = Bv*Hv*8;
    aff_ls8_kernel<<<G8, 128>>>(phi, aff);                                    // 2

    int BS = Hv*Wv*Kv;
    msgpass_ls8_kernel<<<G8, 128>>>(A0,  0,  aff, r1);                        // 3 <- ncu
    msgpass_ls8_kernel<<<G8, 128>>>(r1,  BS, aff, phi);                       // 4
    msgpass_ls8_kernel<<<G8, 128>>>(phi, BS, aff, r1);                        // 5
    msgpass_ls8_kernel<<<G8, 128>>>(r1,  BS, aff, phi);                       // 6
    msgpass_ls8_kernel<<<G8, 128>>>(phi, BS, aff, r1);                        // 7
    msgpass_ls8_kernel<<<G8, 128>>>(r1,  BS, aff, phi);                       // 8
    msgpass_ls8_kernel<<<G8, 128>>>(phi, BS, aff, r1);                        // 9
    msgpass_ls8_kernel<<<G8, 128>>>(r1,  BS, aff, outA);                      // 10

    pool1_kernel<<<Bv*Hv, 256>>>(outA, X, part);                              // 11
    pool2_kernel<<<Bv*Kv, 128>>>(part, outT);                                 // 12
}